// round 15
// baseline (speedup 1.0000x reference)
#include <cuda_runtime.h>

// SOPTD: two tiny MLPs + scalar ODE arithmetic. One warp, serial dataflow.
// FINAL (R13): minimum-instruction single-warp kernel. Evidence across R4-R10
// shows duration is launch-overhead + session-DVFS bound (~6us floor, ±1.5us
// session variance); this variant minimizes the only controllable terms:
//  - front-batched register prefetch of all weights (one memory exposure,
//    every LDG a full coalesced 128B line)
//  - tanh.approx.f32 / rcp.approx.f32 (single MUFU-class activations)
//  - 4-way multi-accumulator shuffle reductions for the 32-wide layers
//  - serial ODE fold (alpha*u6+beta) with partial-g1 precompute
//  - immediate out[0] store; branch-minimal 4-lane store tail
//
// Input order (metadata.txt):
//  0:t  1:states  2:W1 3:b1  4:W2 5:b2  6:W3 7:b3  8:W4 9:b4
//  10:W5 11:b5  12:W6 13:b6  14:W7 15:b7  16:W8 17:b8
//  18:Kp1 19:Kp2 20:Tau1 21:Tau2 22:z1 23:z2
// Output: 5 float32.

__device__ __forceinline__ float htanh(float x) {
    float r;
    asm("tanh.approx.f32 %0, %1;" : "=f"(r) : "f"(x));
    return r;
}

__device__ __forceinline__ float frcp(float x) {
    float r;
    asm("rcp.approx.f32 %0, %1;" : "=f"(r) : "f"(x));
    return r;
}

__global__ __launch_bounds__(32, 1)
void soptd_kernel(const float* __restrict__ states,
                  const float* __restrict__ W1, const float* __restrict__ b1,
                  const float* __restrict__ W2, const float* __restrict__ b2,
                  const float* __restrict__ W3, const float* __restrict__ b3,
                  const float* __restrict__ W4, const float* __restrict__ b4,
                  const float* __restrict__ W5, const float* __restrict__ b5,
                  const float* __restrict__ W6, const float* __restrict__ b6,
                  const float* __restrict__ W7, const float* __restrict__ b7,
                  const float* __restrict__ W8, const float* __restrict__ b8,
                  const float* __restrict__ pKp1, const float* __restrict__ pKp2,
                  const float* __restrict__ pTau1, const float* __restrict__ pTau2,
                  const float* __restrict__ pz1,  const float* __restrict__ pz2,
                  float* __restrict__ out)
{
    const unsigned FULL = 0xffffffffu;
    const int j = threadIdx.x;           // 0..31, one hidden unit per lane

    // out[0] = 0 is input-independent: store immediately (off critical path)
    if (j == 0) out[0] = 0.0f;

    // ======== FRONT-BATCHED LOADS (all independent, issue once) ========
    const float u    = states[0];
    const float x1   = states[1];
    const float x2   = states[2];
    const float x1_p = states[3];
    const float x2_p = states[4];

    const float4 w1a = ((const float4*)W1)[0];
    const float4 w1b = ((const float4*)W1)[1];
    const float4 w1c = ((const float4*)W1)[2];
    const float4 b1v = ((const float4*)b1)[0];

    float w2c[4];
#pragma unroll
    for (int k = 0; k < 4;  ++k) w2c[k] = W2[k*32 + j];
    const float b2c = b2[j];

    float w3c[32];
#pragma unroll
    for (int k = 0; k < 32; ++k) w3c[k] = W3[k*32 + j];
    const float b3c = b3[j];

    const float2 w4v = ((const float2*)W4)[j];
    const float2 b4v = ((const float2*)b4)[0];

    const float Kp1  = *pKp1,  Kp2  = *pKp2;
    const float Tau1 = *pTau1, Tau2 = *pTau2;
    const float z1   = *pz1,   z2   = *pz2;

    float w5c[5];
#pragma unroll
    for (int k = 0; k < 5;  ++k) w5c[k] = W5[k*32 + j];
    const float b5c = b5[j];

    float w6c[32];
#pragma unroll
    for (int k = 0; k < 32; ++k) w6c[k] = W6[k*32 + j];
    const float b6c = b6[j];

    float w7c[32];
#pragma unroll
    for (int k = 0; k < 32; ++k) w7c[k] = W7[k*32 + j];
    const float b7c = b7[j];

    const float4 w8v = ((const float4*)W8)[j];
    const float4 b8v = ((const float4*)b8)[0];

    // cheap independent scalar precompute (few instructions, no reductions)
    const float inv_t1 = frcp(Tau1);
    const float inv_t2 = frcp(Tau2);
    const float alpha1 = Kp1 * inv_t1 * inv_t1;
    const float alpha2 = Kp2 * inv_t2 * inv_t2;
    const float beta1  = (-2.0f * (z1 * x1) - x1_p * inv_t1) * inv_t1;
    const float beta2  = (-2.0f * (z2 * x2) - x2_p * inv_t2) * inv_t2;
    // partial g1 (terms known before u6)
    const float g1k = fmaf(u, w5c[4], fmaf(x2_p, w5c[1], fmaf(x1_p, w5c[0], b5c)));

    // =========== MLP 1: [u,x1,x2] -> 4 -> 32 -> 32 -> 2 ===========
    float h1[4];
    h1[0] = fmaf(u, w1a.x, fmaf(x1, w1b.x, fmaf(x2, w1c.x, b1v.x)));
    h1[1] = fmaf(u, w1a.y, fmaf(x1, w1b.y, fmaf(x2, w1c.y, b1v.y)));
    h1[2] = fmaf(u, w1a.z, fmaf(x1, w1b.z, fmaf(x2, w1c.z, b1v.z)));
    h1[3] = fmaf(u, w1a.w, fmaf(x1, w1b.w, fmaf(x2, w1c.w, b1v.w)));

    float h2 = b2c;
#pragma unroll
    for (int k = 0; k < 4; ++k)
        h2 = fmaf(h1[k], w2c[k], h2);
    h2 = htanh(h2);

    // L3 (32->32, tanh): 4-way multi-accumulator
    float c0=0.f,c1=0.f,c2=0.f,c3=0.f;
#pragma unroll
    for (int k = 0; k < 32; k += 4) {
        c0 = fmaf(__shfl_sync(FULL, h2, k+0), w3c[k+0], c0);
        c1 = fmaf(__shfl_sync(FULL, h2, k+1), w3c[k+1], c1);
        c2 = fmaf(__shfl_sync(FULL, h2, k+2), w3c[k+2], c2);
        c3 = fmaf(__shfl_sync(FULL, h2, k+3), w3c[k+3], c3);
    }
    const float h3 = htanh(b3c + ((c0 + c1) + (c2 + c3)));

    // L4 (32->2): two independent butterfly chains
    float p0 = h3 * w4v.x;
    float p1 = h3 * w4v.y;
#pragma unroll
    for (int off = 16; off > 0; off >>= 1) {
        p0 += __shfl_xor_sync(FULL, p0, off);
        p1 += __shfl_xor_sync(FULL, p1, off);
    }
    const float u60 = p0 + b4v.x;
    const float u61 = p1 + b4v.y;

    // =========== scalar ODE (serial; short) ===========
    const float x1_p_dot = fmaf(alpha1, u60, beta1);
    const float x2_p_dot = fmaf(alpha2, u61, beta2);

    // =========== MLP 2: g1 complete, then single L6 reduction ===========
    const float g1 = fmaf(x1_p_dot, w5c[2], fmaf(x2_p_dot, w5c[3], g1k));

    float s0=0.f,s1=0.f,s2=0.f,s3=0.f;
#pragma unroll
    for (int k = 0; k < 32; k += 4) {
        s0 = fmaf(__shfl_sync(FULL, g1, k+0), w6c[k+0], s0);
        s1 = fmaf(__shfl_sync(FULL, g1, k+1), w6c[k+1], s1);
        s2 = fmaf(__shfl_sync(FULL, g1, k+2), w6c[k+2], s2);
        s3 = fmaf(__shfl_sync(FULL, g1, k+3), w6c[k+3], s3);
    }
    const float g2 = htanh(b6c + ((s0 + s1) + (s2 + s3)));

    // L7 (32->32, tanh)
    float d0=0.f,d1=0.f,d2=0.f,d3=0.f;
#pragma unroll
    for (int k = 0; k < 32; k += 4) {
        d0 = fmaf(__shfl_sync(FULL, g2, k+0), w7c[k+0], d0);
        d1 = fmaf(__shfl_sync(FULL, g2, k+1), w7c[k+1], d1);
        d2 = fmaf(__shfl_sync(FULL, g2, k+2), w7c[k+2], d2);
        d3 = fmaf(__shfl_sync(FULL, g2, k+3), w7c[k+3], d3);
    }
    const float g3 = htanh(b7c + ((d0 + d1) + (d2 + d3)));

    // L8 (32->4): four independent butterfly chains
    float q0 = g3 * w8v.x;
    float q1 = g3 * w8v.y;
    float q2 = g3 * w8v.z;
    float q3 = g3 * w8v.w;
#pragma unroll
    for (int off = 16; off > 0; off >>= 1) {
        q0 += __shfl_xor_sync(FULL, q0, off);
        q1 += __shfl_xor_sync(FULL, q1, off);
        q2 += __shfl_xor_sync(FULL, q2, off);
        q3 += __shfl_xor_sync(FULL, q3, off);
    }

    // out[1..4] = q + b8, one store per lane 1..4
    if (j >= 1 && j <= 4) {
        float val;
        if      (j == 1) val = q0 + b8v.x;
        else if (j == 2) val = q1 + b8v.y;
        else if (j == 3) val = q2 + b8v.z;
        else             val = q3 + b8v.w;
        out[j] = val;
    }
}

extern "C" void kernel_launch(void* const* d_in, const int* in_sizes, int n_in,
                              void* d_out, int out_size)
{
    (void)in_sizes; (void)n_in; (void)out_size;
    soptd_kernel<<<1, 32>>>(
        (const float*)d_in[1],                       // states  (d_in[0] = t, unused)
        (const float*)d_in[2],  (const float*)d_in[3],   // W1 b1
        (const float*)d_in[4],  (const float*)d_in[5],   // W2 b2
        (const float*)d_in[6],  (const float*)d_in[7],   // W3 b3
        (const float*)d_in[8],  (const float*)d_in[9],   // W4 b4
        (const float*)d_in[10], (const float*)d_in[11],  // W5 b5
        (const float*)d_in[12], (const float*)d_in[13],  // W6 b6
        (const float*)d_in[14], (const float*)d_in[15],  // W7 b7
        (const float*)d_in[16], (const float*)d_in[17],  // W8 b8
        (const float*)d_in[18], (const float*)d_in[19],  // Kp1 Kp2
        (const float*)d_in[20], (const float*)d_in[21],  // Tau1 Tau2
        (const float*)d_in[22], (const float*)d_in[23],  // z1 z2
        (float*)d_out);
}

// round 17
// speedup vs baseline: 1.3861x; 1.3861x over previous
#include <cuda_runtime.h>

// SOPTD: two tiny MLPs + scalar ODE arithmetic. One warp, serial dataflow.
// FINAL: minimum-instruction single-warp kernel. Duration is launch-overhead
// + session-DVFS bound (~6us floor, +-1.5us session variance); this variant
// minimizes the only controllable terms:
//  - front-batched register prefetch of all weights (one memory exposure,
//    every LDG a full coalesced 128B line)
//  - tanh.approx.f32 / rcp.approx.f32 (single MUFU-class activations)
//  - 4-way multi-accumulator shuffle reductions for the 32-wide layers
//  - serial ODE fold (alpha*u6+beta) with partial-g1 precompute
//  - immediate out[0] store; branch-minimal 4-lane store tail
//
// Input order (metadata.txt):
//  0:t  1:states  2:W1 3:b1  4:W2 5:b2  6:W3 7:b3  8:W4 9:b4
//  10:W5 11:b5  12:W6 13:b6  14:W7 15:b7  16:W8 17:b8
//  18:Kp1 19:Kp2 20:Tau1 21:Tau2 22:z1 23:z2
// Output: 5 float32.

__device__ __forceinline__ float htanh(float x) {
    float r;
    asm("tanh.approx.f32 %0, %1;" : "=f"(r) : "f"(x));
    return r;
}

__device__ __forceinline__ float frcp(float x) {
    float r;
    asm("rcp.approx.f32 %0, %1;" : "=f"(r) : "f"(x));
    return r;
}

__global__ __launch_bounds__(32, 1)
void soptd_kernel(const float* __restrict__ states,
                  const float* __restrict__ W1, const float* __restrict__ b1,
                  const float* __restrict__ W2, const float* __restrict__ b2,
                  const float* __restrict__ W3, const float* __restrict__ b3,
                  const float* __restrict__ W4, const float* __restrict__ b4,
                  const float* __restrict__ W5, const float* __restrict__ b5,
                  const float* __restrict__ W6, const float* __restrict__ b6,
                  const float* __restrict__ W7, const float* __restrict__ b7,
                  const float* __restrict__ W8, const float* __restrict__ b8,
                  const float* __restrict__ pKp1, const float* __restrict__ pKp2,
                  const float* __restrict__ pTau1, const float* __restrict__ pTau2,
                  const float* __restrict__ pz1,  const float* __restrict__ pz2,
                  float* __restrict__ out)
{
    const unsigned FULL = 0xffffffffu;
    const int j = threadIdx.x;           // 0..31, one hidden unit per lane

    // out[0] = 0 is input-independent: store immediately (off critical path)
    if (j == 0) out[0] = 0.0f;

    // ======== FRONT-BATCHED LOADS (all independent, issue once) ========
    const float u    = states[0];
    const float x1   = states[1];
    const float x2   = states[2];
    const float x1_p = states[3];
    const float x2_p = states[4];

    const float4 w1a = ((const float4*)W1)[0];
    const float4 w1b = ((const float4*)W1)[1];
    const float4 w1c = ((const float4*)W1)[2];
    const float4 b1v = ((const float4*)b1)[0];

    float w2c[4];
#pragma unroll
    for (int k = 0; k < 4;  ++k) w2c[k] = W2[k*32 + j];
    const float b2c = b2[j];

    float w3c[32];
#pragma unroll
    for (int k = 0; k < 32; ++k) w3c[k] = W3[k*32 + j];
    const float b3c = b3[j];

    const float2 w4v = ((const float2*)W4)[j];
    const float2 b4v = ((const float2*)b4)[0];

    const float Kp1  = *pKp1,  Kp2  = *pKp2;
    const float Tau1 = *pTau1, Tau2 = *pTau2;
    const float z1   = *pz1,   z2   = *pz2;

    float w5c[5];
#pragma unroll
    for (int k = 0; k < 5;  ++k) w5c[k] = W5[k*32 + j];
    const float b5c = b5[j];

    float w6c[32];
#pragma unroll
    for (int k = 0; k < 32; ++k) w6c[k] = W6[k*32 + j];
    const float b6c = b6[j];

    float w7c[32];
#pragma unroll
    for (int k = 0; k < 32; ++k) w7c[k] = W7[k*32 + j];
    const float b7c = b7[j];

    const float4 w8v = ((const float4*)W8)[j];
    const float4 b8v = ((const float4*)b8)[0];

    // cheap independent scalar precompute (few instructions, no reductions)
    const float inv_t1 = frcp(Tau1);
    const float inv_t2 = frcp(Tau2);
    const float alpha1 = Kp1 * inv_t1 * inv_t1;
    const float alpha2 = Kp2 * inv_t2 * inv_t2;
    const float beta1  = (-2.0f * (z1 * x1) - x1_p * inv_t1) * inv_t1;
    const float beta2  = (-2.0f * (z2 * x2) - x2_p * inv_t2) * inv_t2;
    // partial g1 (terms known before u6)
    const float g1k = fmaf(u, w5c[4], fmaf(x2_p, w5c[1], fmaf(x1_p, w5c[0], b5c)));

    // =========== MLP 1: [u,x1,x2] -> 4 -> 32 -> 32 -> 2 ===========
    float h1[4];
    h1[0] = fmaf(u, w1a.x, fmaf(x1, w1b.x, fmaf(x2, w1c.x, b1v.x)));
    h1[1] = fmaf(u, w1a.y, fmaf(x1, w1b.y, fmaf(x2, w1c.y, b1v.y)));
    h1[2] = fmaf(u, w1a.z, fmaf(x1, w1b.z, fmaf(x2, w1c.z, b1v.z)));
    h1[3] = fmaf(u, w1a.w, fmaf(x1, w1b.w, fmaf(x2, w1c.w, b1v.w)));

    float h2 = b2c;
#pragma unroll
    for (int k = 0; k < 4; ++k)
        h2 = fmaf(h1[k], w2c[k], h2);
    h2 = htanh(h2);

    // L3 (32->32, tanh): 4-way multi-accumulator
    float c0=0.f,c1=0.f,c2=0.f,c3=0.f;
#pragma unroll
    for (int k = 0; k < 32; k += 4) {
        c0 = fmaf(__shfl_sync(FULL, h2, k+0), w3c[k+0], c0);
        c1 = fmaf(__shfl_sync(FULL, h2, k+1), w3c[k+1], c1);
        c2 = fmaf(__shfl_sync(FULL, h2, k+2), w3c[k+2], c2);
        c3 = fmaf(__shfl_sync(FULL, h2, k+3), w3c[k+3], c3);
    }
    const float h3 = htanh(b3c + ((c0 + c1) + (c2 + c3)));

    // L4 (32->2): two independent butterfly chains
    float p0 = h3 * w4v.x;
    float p1 = h3 * w4v.y;
#pragma unroll
    for (int off = 16; off > 0; off >>= 1) {
        p0 += __shfl_xor_sync(FULL, p0, off);
        p1 += __shfl_xor_sync(FULL, p1, off);
    }
    const float u60 = p0 + b4v.x;
    const float u61 = p1 + b4v.y;

    // =========== scalar ODE (serial; short) ===========
    const float x1_p_dot = fmaf(alpha1, u60, beta1);
    const float x2_p_dot = fmaf(alpha2, u61, beta2);

    // =========== MLP 2: g1 complete, then single L6 reduction ===========
    const float g1 = fmaf(x1_p_dot, w5c[2], fmaf(x2_p_dot, w5c[3], g1k));

    float s0=0.f,s1=0.f,s2=0.f,s3=0.f;
#pragma unroll
    for (int k = 0; k < 32; k += 4) {
        s0 = fmaf(__shfl_sync(FULL, g1, k+0), w6c[k+0], s0);
        s1 = fmaf(__shfl_sync(FULL, g1, k+1), w6c[k+1], s1);
        s2 = fmaf(__shfl_sync(FULL, g1, k+2), w6c[k+2], s2);
        s3 = fmaf(__shfl_sync(FULL, g1, k+3), w6c[k+3], s3);
    }
    const float g2 = htanh(b6c + ((s0 + s1) + (s2 + s3)));

    // L7 (32->32, tanh)
    float d0=0.f,d1=0.f,d2=0.f,d3=0.f;
#pragma unroll
    for (int k = 0; k < 32; k += 4) {
        d0 = fmaf(__shfl_sync(FULL, g2, k+0), w7c[k+0], d0);
        d1 = fmaf(__shfl_sync(FULL, g2, k+1), w7c[k+1], d1);
        d2 = fmaf(__shfl_sync(FULL, g2, k+2), w7c[k+2], d2);
        d3 = fmaf(__shfl_sync(FULL, g2, k+3), w7c[k+3], d3);
    }
    const float g3 = htanh(b7c + ((d0 + d1) + (d2 + d3)));

    // L8 (32->4): four independent butterfly chains
    float q0 = g3 * w8v.x;
    float q1 = g3 * w8v.y;
    float q2 = g3 * w8v.z;
    float q3 = g3 * w8v.w;
#pragma unroll
    for (int off = 16; off > 0; off >>= 1) {
        q0 += __shfl_xor_sync(FULL, q0, off);
        q1 += __shfl_xor_sync(FULL, q1, off);
        q2 += __shfl_xor_sync(FULL, q2, off);
        q3 += __shfl_xor_sync(FULL, q3, off);
    }

    // out[1..4] = q + b8, one store per lane 1..4
    if (j >= 1 && j <= 4) {
        float val;
        if      (j == 1) val = q0 + b8v.x;
        else if (j == 2) val = q1 + b8v.y;
        else if (j == 3) val = q2 + b8v.z;
        else             val = q3 + b8v.w;
        out[j] = val;
    }
}

extern "C" void kernel_launch(void* const* d_in, const int* in_sizes, int n_in,
                              void* d_out, int out_size)
{
    (void)in_sizes; (void)n_in; (void)out_size;
    soptd_kernel<<<1, 32>>>(
        (const float*)d_in[1],                       // states  (d_in[0] = t, unused)
        (const float*)d_in[2],  (const float*)d_in[3],   // W1 b1
        (const float*)d_in[4],  (const float*)d_in[5],   // W2 b2
        (const float*)d_in[6],  (const float*)d_in[7],   // W3 b3
        (const float*)d_in[8],  (const float*)d_in[9],   // W4 b4
        (const float*)d_in[10], (const float*)d_in[11],  // W5 b5
        (const float*)d_in[12], (const float*)d_in[13],  // W6 b6
        (const float*)d_in[14], (const float*)d_in[15],  // W7 b7
        (const float*)d_in[16], (const float*)d_in[17],  // W8 b8
        (const float*)d_in[18], (const float*)d_in[19],  // Kp1 Kp2
        (const float*)d_in[20], (const float*)d_in[21],  // Tau1 Tau2
        (const float*)d_in[22], (const float*)d_in[23],  // z1 z2
        (float*)d_out);
}